// round 7
// baseline (speedup 1.0000x reference)
#include <cuda_runtime.h>
#include <math.h>

#define H   256
#define HD  64
#define Bb  2
#define Qq  8
#define Tt  512
#define NP  256          // number of timestep pairs
#define EB  16
#define BT  1024
#define NEGc (-0.6065306597126334f)
#define EPSc 0.00064f

// ---------------- scratch (device globals; no allocations) ----------------
__device__ float g_K  [BT*H];
__device__ float g_Vb [BT*H];
__device__ float g_sigv[BT*H];
__device__ float g_hA [BT*H];
__device__ float g_Hw1[BT*32];
__device__ float g_qw1[EB*32];
__device__ float g_qA [EB*H];
__device__ float g_rlast[EB*H];
__device__ float g_glast[EB*H];
__device__ float g_o  [EB*H];
__device__ float4 g_Pa [(size_t)EB*NP*H];   // {kf1, bv1, F1=ew1*kf0, F2=ew1*bv0}
__device__ float4 g_Pb [(size_t)EB*NP*H];   // {E=ew1*ew0, G=kk1*ew0, kk0, vv1}
__device__ float  g_Pv0[(size_t)EB*NP*H];   // vv0
__device__ float2 g_q  [EB*NP*4];           // per-head {q1=kk1·kf0, q2=kk1·bv0}

__device__ __forceinline__ float sigmoidf_(float x) { return 1.f / (1.f + __expf(-x)); }

__device__ __forceinline__ float wsum(float v) {
    #pragma unroll
    for (int o = 16; o; o >>= 1) v += __shfl_xor_sync(0xffffffffu, v, o);
    return v;
}

// ---------------- k1: merged per-bt and per-eb small chains ----------------
__global__ void k_btq(const float* __restrict__ keyval, const float* __restrict__ query,
                      const float* __restrict__ x_v, const float* __restrict__ x_w,
                      const float* __restrict__ x_a, const float* __restrict__ x_r,
                      const float* __restrict__ x_g,
                      const float* __restrict__ w1, const float* __restrict__ v1,
                      const float* __restrict__ a1, const float* __restrict__ v2,
                      const float* __restrict__ a2, const float* __restrict__ v0,
                      const float* __restrict__ g1, const float* __restrict__ g2,
                      const float* __restrict__ Wr) {
    int blk = blockIdx.x;
    int j = threadIdx.x;
    int w = j >> 5, ln = j & 31;
    __shared__ float s0[H], s1[H], s2[H], s3[H];
    __shared__ float red[4][8][32];
    __shared__ float mid[4][32];
    if (blk < BT) {
        // ---- per-(b,t) role ----
        int bt = blk, t = bt & (Tt - 1);
        float hs = keyval[bt*H + j];
        float hp = (t > 0) ? keyval[(bt-1)*H + j] : 0.f;
        s0[j] = fmaf(hp - hs, x_v[j], hs);   // xv
        s1[j] = hs * (1.f - x_w[j]);         // xwh
        s2[j] = hs * (1.f - x_a[j]);         // xah
        __syncthreads();
        int kbase = w * 32;
        float pw = 0.f, pv = 0.f, pa = 0.f;
        #pragma unroll
        for (int kk = 0; kk < 32; kk++) {
            int k = kbase + kk;
            pw = fmaf(s1[k], w1[k*32 + ln], pw);
            pv = fmaf(s0[k], v1[k*32 + ln], pv);
            pa = fmaf(s2[k], a1[k*32 + ln], pa);
        }
        red[0][w][ln] = pw; red[1][w][ln] = pv; red[2][w][ln] = pa;
        __syncthreads();
        if (j < 96) {
            int m = j >> 5, d = j & 31;
            float s = 0.f;
            #pragma unroll
            for (int ww = 0; ww < 8; ww++) s += red[m][ww][d];
            mid[m][d] = s;
            if (m == 0) g_Hw1[bt*32 + d] = s;
        }
        __syncthreads();
        float av = 0.f, aa = 0.f;
        #pragma unroll
        for (int d = 0; d < 32; d++) {
            av = fmaf(mid[1][d], v2[d*H + j], av);
            aa = fmaf(mid[2][d], a2[d*H + j], aa);
        }
        g_sigv[bt*H + j] = sigmoidf_(av + v0[j]);
        g_hA[bt*H + j]   = aa;
    } else {
        // ---- per-eb role ----
        int eb = blk - BT; int b = eb >> 3;
        float qv  = query[eb*H + j];
        float hsL = keyval[(b*Tt + Tt - 1)*H + j];
        s0[j] = fmaf(qv - hsL, x_r[j], hsL);  // xr
        s1[j] = fmaf(qv - hsL, x_g[j], hsL);  // xg
        s2[j] = qv * x_w[j];                  // xw (query part)
        s3[j] = qv * x_a[j];                  // xa (query part)
        __syncthreads();
        int kbase = w * 32;
        float pw = 0.f, pa = 0.f, pg0 = 0.f, pg1 = 0.f;
        #pragma unroll
        for (int kk = 0; kk < 32; kk++) {
            int k = kbase + kk;
            pw  = fmaf(s2[k], w1[k*32 + ln], pw);
            pa  = fmaf(s3[k], a1[k*32 + ln], pa);
            pg0 = fmaf(s1[k], g1[k*64 + ln], pg0);
            pg1 = fmaf(s1[k], g1[k*64 + 32 + ln], pg1);
        }
        red[0][w][ln] = pw; red[1][w][ln] = pa; red[2][w][ln] = pg0; red[3][w][ln] = pg1;
        __syncthreads();
        if (j < 128) {
            int m = j >> 5, d = j & 31;
            float s = 0.f;
            #pragma unroll
            for (int ww = 0; ww < 8; ww++) s += red[m][ww][d];
            if      (m == 0) g_qw1[eb*32 + d] = s;
            else if (m == 1) mid[1][d] = s;               // ta
            else if (m == 2) mid[2][d] = sigmoidf_(s);    // tg[0:32]
            else             mid[3][d] = sigmoidf_(s);    // tg[32:64]
        }
        __syncthreads();
        float aa = 0.f, gg = 0.f;
        #pragma unroll
        for (int d = 0; d < 32; d++) {
            aa = fmaf(mid[1][d], a2[d*H + j], aa);
            gg = fmaf(mid[2][d], g2[d*H + j], gg);
        }
        #pragma unroll
        for (int d = 0; d < 32; d++) gg = fmaf(mid[3][d], g2[(32 + d)*H + j], gg);
        g_qA[eb*H + j]    = aa;
        g_glast[eb*H + j] = gg;
        // rlast: per-thread row dot (no warp reductions)
        float acc = 0.f;
        const float4* __restrict__ Wrow = (const float4*)(Wr + j*H);
        #pragma unroll 16
        for (int k4 = 0; k4 < 64; k4++) {
            float4 wv = Wrow[k4];
            acc += s0[4*k4]*wv.x + s0[4*k4+1]*wv.y + s0[4*k4+2]*wv.z + s0[4*k4+3]*wv.w;
        }
        g_rlast[eb*H + j] = acc;
    }
}

// ---------------- k2: K = Xk@Wk^T, Vb = Xv@Wv^T (Xk/Xv built on the fly) ----------------
__global__ void k_gemm_kv(const float* __restrict__ keyval,
                          const float* __restrict__ x_k, const float* __restrict__ x_v,
                          const float* __restrict__ Wk, const float* __restrict__ Wv) {
    const int z = blockIdx.z;
    const float* __restrict__ xm = z ? x_v : x_k;
    const float* __restrict__ W  = z ? Wv  : Wk;
    float* __restrict__ C = z ? g_Vb : g_K;
    __shared__ float As[64][33];
    __shared__ float Ws[64][33];
    int tid = threadIdx.x;
    int tx = tid & 15, ty = tid >> 4;
    int bm = blockIdx.x * 64, bn = blockIdx.y * 64;
    float acc[4][4] = {};
    #pragma unroll 1
    for (int k0 = 0; k0 < H; k0 += 32) {
        #pragma unroll
        for (int l = tid; l < 64*32; l += 256) {
            int r = l >> 5, c = l & 31;
            int m = bm + r, kg = k0 + c;
            int t = m & (Tt - 1);
            float hs = keyval[m*H + kg];
            float hp = (t > 0) ? keyval[(m-1)*H + kg] : 0.f;
            As[r][c] = fmaf(hp - hs, __ldg(&xm[kg]), hs);
            Ws[r][c] = W[(bn + r)*H + kg];
        }
        __syncthreads();
        #pragma unroll
        for (int kk = 0; kk < 32; kk++) {
            float a_[4], w_[4];
            #pragma unroll
            for (int i = 0; i < 4; i++) { a_[i] = As[ty + 16*i][kk]; w_[i] = Ws[tx + 16*i][kk]; }
            #pragma unroll
            for (int i = 0; i < 4; i++)
                #pragma unroll
                for (int jj = 0; jj < 4; jj++) acc[i][jj] = fmaf(a_[i], w_[jj], acc[i][jj]);
        }
        __syncthreads();
    }
    #pragma unroll
    for (int i = 0; i < 4; i++)
        #pragma unroll
        for (int jj = 0; jj < 4; jj++)
            C[(bm + ty + 16*i)*H + (bn + tx + 16*jj)] = acc[i][jj];
}

// ---------------- k3: per-(eb, pair) scan-input precompute (kk-normalize inline) ----------------
__global__ void k_pair(const float* __restrict__ v_first, const float* __restrict__ w2,
                       const float* __restrict__ w0, const float* __restrict__ a0,
                       const float* __restrict__ k_a, const float* __restrict__ k_k) {
    int p = blockIdx.x, eb = blockIdx.y;
    int b = eb >> 3;
    int t1 = 2*p + 1, t0 = 2*p;
    int bt1 = b*Tt + t1, bt0 = b*Tt + t0;
    int j = threadIdx.x;
    int w = j >> 5, ln = j & 31;
    __shared__ float th[2][32];
    __shared__ float wsq[2][8];
    __shared__ float sq[2][8];
    // kk-normalize partials (per-bt)
    float kkj = k_k[j];
    float kkv1 = g_K[bt1*H + j] * kkj;
    float kkv0 = g_K[bt0*H + j] * kkj;
    float n1p = wsum(kkv1 * kkv1);
    float n0p = wsum(kkv0 * kkv0);
    if (ln == 0) { wsq[0][w] = n1p; wsq[1][w] = n0p; }
    if (j < 64) {
        int m = j >> 5, d = j & 31;
        int btx = m ? bt0 : bt1;
        th[m][d] = tanhf(g_Hw1[btx*32 + d] + g_qw1[eb*32 + d]);
    }
    __syncthreads();
    int head = j >> 6;
    float nrm1 = sqrtf(wsq[0][2*head] + wsq[0][2*head + 1]);
    float nrm0 = sqrtf(wsq[1][2*head] + wsq[1][2*head + 1]);
    float kk1 = kkv1 / fmaxf(nrm1, 1e-12f);
    float kk0 = kkv0 / fmaxf(nrm0, 1e-12f);
    float ac1 = 0.f, ac0 = 0.f;
    #pragma unroll
    for (int d = 0; d < 32; d++) {
        float wd = w2[d*H + j];
        ac1 = fmaf(th[0][d], wd, ac1);
        ac0 = fmaf(th[1][d], wd, ac0);
    }
    float w0j = w0[j], a0j = a0[j], kaj = k_a[j], qAj = g_qA[eb*H + j];
    float ew1 = __expf(NEGc * sigmoidf_(w0j + ac1));
    float ew0 = __expf(NEGc * sigmoidf_(w0j + ac0));
    float a41 = sigmoidf_(a0j + g_hA[bt1*H + j] + qAj);
    float a40 = sigmoidf_(a0j + g_hA[bt0*H + j] + qAj);
    float kf1 = g_K[bt1*H + j] * fmaf(a41 - 1.f, kaj, 1.f);
    float kf0 = g_K[bt0*H + j] * fmaf(a40 - 1.f, kaj, 1.f);
    float bv1 = kk1 * a41;
    float bv0 = kk0 * a40;
    float vb1 = g_Vb[bt1*H + j], sv1 = g_sigv[bt1*H + j];
    float vb0 = g_Vb[bt0*H + j], sv0 = g_sigv[bt0*H + j];
    float vv1 = fmaf(v_first[((size_t)eb*Tt + t1)*H + j] - vb1, sv1, vb1);
    float vv0 = fmaf(v_first[((size_t)eb*Tt + t0)*H + j] - vb0, sv0, vb0);
    size_t idx = ((size_t)eb*NP + p)*H + j;
    g_Pa[idx]  = make_float4(kf1, bv1, ew1*kf0, ew1*bv0);
    g_Pb[idx]  = make_float4(ew1*ew0, kk1*ew0, kk0, vv1);
    g_Pv0[idx] = vv0;
    float q1p = wsum(kk1 * kf0);
    float q2p = wsum(kk1 * bv0);
    if (ln == 0) { sq[0][w] = q1p; sq[1][w] = q2p; }
    __syncthreads();
    if (j < 4) {
        float q1 = sq[0][2*j] + sq[0][2*j + 1];
        float q2 = sq[1][2*j] + sq[1][2*j + 1];
        g_q[(eb*NP + p)*4 + j] = make_float2(q1, q2);
    }
}

// ---------------- k4: backward scan, 1 warp per (eb, head), 4-deep prefetch ----------------
#define PF 4
__global__ void __launch_bounds__(32, 4) k_scan(const float* __restrict__ r_k,
                       const float* __restrict__ gn_w, const float* __restrict__ gn_b) {
    int wb = blockIdx.x;
    int eb = wb >> 2, h = wb & 3;
    int ln = threadIdx.x;
    int i0 = h*HD + ln, i1 = i0 + 32;
    float u0 = g_rlast[eb*H + i0], u1 = g_rlast[eb*H + i1];
    float o0 = 0.f, o1 = 0.f;
    const float4* __restrict__ Pa  = g_Pa  + (size_t)eb*NP*H;
    const float4* __restrict__ Pb  = g_Pb  + (size_t)eb*NP*H;
    const float*  __restrict__ Pv0 = g_Pv0 + (size_t)eb*NP*H;
    const float2* __restrict__ Qs  = g_q   + eb*NP*4;

    float4 A0[PF], A1[PF], B0[PF], B1[PF];
    float  V0[PF], V1[PF];
    float2 Qr[PF];
    #pragma unroll
    for (int s = 0; s < PF; s++) {
        int p = NP - 1 - s;
        size_t base = (size_t)p*H;
        A0[s] = Pa[base + i0]; A1[s] = Pa[base + i1];
        B0[s] = Pb[base + i0]; B1[s] = Pb[base + i1];
        V0[s] = Pv0[base + i0]; V1[s] = Pv0[base + i1];
        Qr[s] = Qs[p*4 + h];
    }
    #pragma unroll 1
    for (int p0 = NP - 1; p0 >= PF - 1; p0 -= PF) {
        #pragma unroll
        for (int s = 0; s < PF; s++) {
            int p = p0 - s;
            float4 cA0 = A0[s], cA1 = A1[s], cB0 = B0[s], cB1 = B1[s];
            float cV0 = V0[s], cV1 = V1[s];
            float2 cQ = Qr[s];
            // L2 prefetch 2*PF pairs ahead
            int pl2 = p - 2*PF;
            if (pl2 >= 0) {
                size_t lb = (size_t)pl2*H;
                asm volatile("prefetch.global.L2 [%0];" :: "l"(Pa + lb + i0));
                asm volatile("prefetch.global.L2 [%0];" :: "l"(Pb + lb + i0));
                asm volatile("prefetch.global.L2 [%0];" :: "l"(Pa + lb + i1));
                asm volatile("prefetch.global.L2 [%0];" :: "l"(Pb + lb + i1));
            }
            // register-ring refill for p-PF
            int pn = p - PF;
            if (pn >= 0) {
                size_t nb = (size_t)pn*H;
                A0[s] = Pa[nb + i0]; A1[s] = Pa[nb + i1];
                B0[s] = Pb[nb + i0]; B1[s] = Pb[nb + i1];
                V0[s] = Pv0[nb + i0]; V1[s] = Pv0[nb + i1];
                Qr[s] = Qs[pn*4 + h];
            }
            // four independent reductions, interleaved butterflies
            float r1 = fmaf(u0, cA0.x, u1*cA1.x);   // c1 = u·kf1
            float r2 = fmaf(u0, cA0.y, u1*cA1.y);   // s1 = u·bv1
            float r3 = fmaf(u0, cA0.z, u1*cA1.z);   // m1 = u·(ew1∘kf0)
            float r4 = fmaf(u0, cA0.w, u1*cA1.w);   // m2 = u·(ew1∘bv0)
            #pragma unroll
            for (int off = 16; off; off >>= 1) {
                r1 += __shfl_xor_sync(0xffffffffu, r1, off);
                r2 += __shfl_xor_sync(0xffffffffu, r2, off);
                r3 += __shfl_xor_sync(0xffffffffu, r3, off);
                r4 += __shfl_xor_sync(0xffffffffu, r4, off);
            }
            float c0 = fmaf(-r2, cQ.x, r3);
            float s0 = fmaf(-r2, cQ.y, r4);
            o0 = fmaf(r1, cB0.w, fmaf(c0, cV0, o0));
            o1 = fmaf(r1, cB1.w, fmaf(c0, cV1, o1));
            u0 = fmaf(u0, cB0.x, -fmaf(r2, cB0.y, s0*cB0.z));
            u1 = fmaf(u1, cB1.x, -fmaf(r2, cB1.y, s0*cB1.z));
        }
    }
    // groupnorm over the head's 64 values
    float ms = wsum(o0 + o1);
    float sqs = wsum(fmaf(o0, o0, o1*o1));
    float mean = ms * (1.f/64.f);
    float var  = sqs * (1.f/64.f) - mean*mean;
    float inv  = rsqrtf(var + EPSc);
    float on0 = fmaf((o0 - mean)*inv, gn_w[i0], gn_b[i0]);
    float on1 = fmaf((o1 - mean)*inv, gn_w[i1], gn_b[i1]);
    // residual at t = T-1 (pair NP-1: kf1 = Pa.x, vv1 = Pb.w)
    size_t lb = (size_t)(NP-1)*H;
    float4 La0 = Pa[lb + i0], La1 = Pa[lb + i1];
    float4 Lb0 = Pb[lb + i0], Lb1 = Pb[lb + i1];
    float r0 = g_rlast[eb*H + i0], r1l = g_rlast[eb*H + i1];
    float rr = wsum(r0*La0.x*r_k[i0] + r1l*La1.x*r_k[i1]);
    on0 = fmaf(rr, Lb0.w, on0);
    on1 = fmaf(rr, Lb1.w, on1);
    g_o[eb*H + i0] = on0 * g_glast[eb*H + i0];
    g_o[eb*H + i1] = on1 * g_glast[eb*H + i1];
}

// ---------------- k5: out = g_o @ Wo^T (per-thread row dot) ----------------
__global__ void k_out(const float* __restrict__ Wo, float* __restrict__ out) {
    int eb = blockIdx.x; int j = threadIdx.x;
    __shared__ float os[H];
    os[j] = g_o[eb*H + j];
    __syncthreads();
    float acc = 0.f;
    const float4* __restrict__ Wrow = (const float4*)(Wo + j*H);
    #pragma unroll 16
    for (int k4 = 0; k4 < 64; k4++) {
        float4 wv = Wrow[k4];
        acc += os[4*k4]*wv.x + os[4*k4+1]*wv.y + os[4*k4+2]*wv.z + os[4*k4+3]*wv.w;
    }
    out[eb*H + j] = acc;
}

// ---------------- launch ----------------
extern "C" void kernel_launch(void* const* d_in, const int* in_sizes, int n_in,
                              void* d_out, int out_size) {
    const float* query   = (const float*)d_in[0];
    const float* keyval  = (const float*)d_in[1];
    const float* v_first = (const float*)d_in[2];
    const float* x_r = (const float*)d_in[3];
    const float* x_w = (const float*)d_in[4];
    const float* x_k = (const float*)d_in[5];
    const float* x_v = (const float*)d_in[6];
    const float* x_a = (const float*)d_in[7];
    const float* x_g = (const float*)d_in[8];
    const float* w0  = (const float*)d_in[9];
    const float* w1  = (const float*)d_in[10];
    const float* w2  = (const float*)d_in[11];
    const float* a0  = (const float*)d_in[12];
    const float* a1  = (const float*)d_in[13];
    const float* a2  = (const float*)d_in[14];
    const float* v0  = (const float*)d_in[15];
    const float* v1  = (const float*)d_in[16];
    const float* v2  = (const float*)d_in[17];
    const float* g1  = (const float*)d_in[18];
    const float* g2  = (const float*)d_in[19];
    const float* k_k = (const float*)d_in[20];
    const float* k_a = (const float*)d_in[21];
    const float* r_k = (const float*)d_in[22];
    const float* Wr  = (const float*)d_in[23];
    const float* Wk  = (const float*)d_in[24];
    const float* Wv  = (const float*)d_in[25];
    const float* Wo  = (const float*)d_in[26];
    const float* gn_w = (const float*)d_in[27];
    const float* gn_b = (const float*)d_in[28];
    float* out = (float*)d_out;

    k_btq<<<BT + EB, H>>>(keyval, query, x_v, x_w, x_a, x_r, x_g,
                          w1, v1, a1, v2, a2, v0, g1, g2, Wr);
    k_gemm_kv<<<dim3(BT/64, H/64, 2), 256>>>(keyval, x_k, x_v, Wk, Wv);
    k_pair<<<dim3(NP, EB), H>>>(v_first, w2, w0, a0, k_a, k_k);
    k_scan<<<EB*4, 32>>>(r_k, gn_w, gn_b);
    k_out<<<EB, H>>>(Wo, out);
    (void)in_sizes; (void)n_in; (void)out_size;
}

// round 8
// speedup vs baseline: 1.1882x; 1.1882x over previous
#include <cuda_runtime.h>
#include <math.h>

#define H   256
#define HD  64
#define Bb  2
#define Qq  8
#define Tt  512
#define NP  256          // number of timestep pairs
#define EB  16
#define BT  1024
#define NEGc (-0.6065306597126334f)
#define EPSc 0.00064f

// ---------------- scratch (device globals; no allocations) ----------------
__device__ float g_K  [BT*H];
__device__ float g_Vb [BT*H];
__device__ float g_sigv[BT*H];
__device__ float g_hA [BT*H];
__device__ float g_Hw1[BT*32];
__device__ float g_qw1[EB*32];
__device__ float g_qA [EB*H];
__device__ float g_rlast[EB*H];
__device__ float g_glast[EB*H];
__device__ float g_o  [EB*H];
__device__ float4 g_Pa [(size_t)EB*NP*H];   // {kf1, bv1, F1=ew1*kf0, F2=ew1*bv0}
__device__ float4 g_Pb [(size_t)EB*NP*H];   // {E=ew1*ew0, G=kk1*ew0, kk0, vv1}
__device__ float  g_Pv0[(size_t)EB*NP*H];   // vv0
__device__ float2 g_q  [EB*NP*4];           // per-head {q1=kk1·kf0, q2=kk1·bv0}

__device__ __forceinline__ float sigmoidf_(float x) { return 1.f / (1.f + __expf(-x)); }

__device__ __forceinline__ float wsum(float v) {
    #pragma unroll
    for (int o = 16; o; o >>= 1) v += __shfl_xor_sync(0xffffffffu, v, o);
    return v;
}

// ---------------- k1: merged per-bt and per-eb small chains ----------------
__global__ void k_btq(const float* __restrict__ keyval, const float* __restrict__ query,
                      const float* __restrict__ x_v, const float* __restrict__ x_w,
                      const float* __restrict__ x_a, const float* __restrict__ x_r,
                      const float* __restrict__ x_g,
                      const float* __restrict__ w1, const float* __restrict__ v1,
                      const float* __restrict__ a1, const float* __restrict__ v2,
                      const float* __restrict__ a2, const float* __restrict__ v0,
                      const float* __restrict__ g1, const float* __restrict__ g2,
                      const float* __restrict__ Wr) {
    int blk = blockIdx.x;
    int j = threadIdx.x;
    int w = j >> 5, ln = j & 31;
    __shared__ float s0[H], s1[H], s2[H], s3[H];
    __shared__ float red[4][8][32];
    __shared__ float mid[4][32];
    if (blk < BT) {
        int bt = blk, t = bt & (Tt - 1);
        float hs = keyval[bt*H + j];
        float hp = (t > 0) ? keyval[(bt-1)*H + j] : 0.f;
        s0[j] = fmaf(hp - hs, x_v[j], hs);   // xv
        s1[j] = hs * (1.f - x_w[j]);         // xwh
        s2[j] = hs * (1.f - x_a[j]);         // xah
        __syncthreads();
        int kbase = w * 32;
        float pw = 0.f, pv = 0.f, pa = 0.f;
        #pragma unroll
        for (int kk = 0; kk < 32; kk++) {
            int k = kbase + kk;
            pw = fmaf(s1[k], w1[k*32 + ln], pw);
            pv = fmaf(s0[k], v1[k*32 + ln], pv);
            pa = fmaf(s2[k], a1[k*32 + ln], pa);
        }
        red[0][w][ln] = pw; red[1][w][ln] = pv; red[2][w][ln] = pa;
        __syncthreads();
        if (j < 96) {
            int m = j >> 5, d = j & 31;
            float s = 0.f;
            #pragma unroll
            for (int ww = 0; ww < 8; ww++) s += red[m][ww][d];
            mid[m][d] = s;
            if (m == 0) g_Hw1[bt*32 + d] = s;
        }
        __syncthreads();
        float av = 0.f, aa = 0.f;
        #pragma unroll
        for (int d = 0; d < 32; d++) {
            av = fmaf(mid[1][d], v2[d*H + j], av);
            aa = fmaf(mid[2][d], a2[d*H + j], aa);
        }
        g_sigv[bt*H + j] = sigmoidf_(av + v0[j]);
        g_hA[bt*H + j]   = aa;
    } else {
        int eb = blk - BT; int b = eb >> 3;
        float qv  = query[eb*H + j];
        float hsL = keyval[(b*Tt + Tt - 1)*H + j];
        s0[j] = fmaf(qv - hsL, x_r[j], hsL);  // xr
        s1[j] = fmaf(qv - hsL, x_g[j], hsL);  // xg
        s2[j] = qv * x_w[j];                  // xw (query part)
        s3[j] = qv * x_a[j];                  // xa (query part)
        __syncthreads();
        int kbase = w * 32;
        float pw = 0.f, pa = 0.f, pg0 = 0.f, pg1 = 0.f;
        #pragma unroll
        for (int kk = 0; kk < 32; kk++) {
            int k = kbase + kk;
            pw  = fmaf(s2[k], w1[k*32 + ln], pw);
            pa  = fmaf(s3[k], a1[k*32 + ln], pa);
            pg0 = fmaf(s1[k], g1[k*64 + ln], pg0);
            pg1 = fmaf(s1[k], g1[k*64 + 32 + ln], pg1);
        }
        red[0][w][ln] = pw; red[1][w][ln] = pa; red[2][w][ln] = pg0; red[3][w][ln] = pg1;
        __syncthreads();
        if (j < 128) {
            int m = j >> 5, d = j & 31;
            float s = 0.f;
            #pragma unroll
            for (int ww = 0; ww < 8; ww++) s += red[m][ww][d];
            if      (m == 0) g_qw1[eb*32 + d] = s;
            else if (m == 1) mid[1][d] = s;               // ta
            else if (m == 2) mid[2][d] = sigmoidf_(s);    // tg[0:32]
            else             mid[3][d] = sigmoidf_(s);    // tg[32:64]
        }
        __syncthreads();
        float aa = 0.f, gg = 0.f;
        #pragma unroll
        for (int d = 0; d < 32; d++) {
            aa = fmaf(mid[1][d], a2[d*H + j], aa);
            gg = fmaf(mid[2][d], g2[d*H + j], gg);
        }
        #pragma unroll
        for (int d = 0; d < 32; d++) gg = fmaf(mid[3][d], g2[(32 + d)*H + j], gg);
        g_qA[eb*H + j]    = aa;
        g_glast[eb*H + j] = gg;
        float acc = 0.f;
        const float4* __restrict__ Wrow = (const float4*)(Wr + j*H);
        #pragma unroll 16
        for (int k4 = 0; k4 < 64; k4++) {
            float4 wv = Wrow[k4];
            acc += s0[4*k4]*wv.x + s0[4*k4+1]*wv.y + s0[4*k4+2]*wv.z + s0[4*k4+3]*wv.w;
        }
        g_rlast[eb*H + j] = acc;
    }
}

// ---------------- k2: K = Xk@Wk^T, Vb = Xv@Wv^T (Xk/Xv built on the fly) ----------------
__global__ void k_gemm_kv(const float* __restrict__ keyval,
                          const float* __restrict__ x_k, const float* __restrict__ x_v,
                          const float* __restrict__ Wk, const float* __restrict__ Wv) {
    const int z = blockIdx.z;
    const float* __restrict__ xm = z ? x_v : x_k;
    const float* __restrict__ W  = z ? Wv  : Wk;
    float* __restrict__ C = z ? g_Vb : g_K;
    __shared__ float As[64][33];
    __shared__ float Ws[64][33];
    int tid = threadIdx.x;
    int tx = tid & 15, ty = tid >> 4;
    int bm = blockIdx.x * 64, bn = blockIdx.y * 64;
    float acc[4][4] = {};
    #pragma unroll 1
    for (int k0 = 0; k0 < H; k0 += 32) {
        #pragma unroll
        for (int l = tid; l < 64*32; l += 256) {
            int r = l >> 5, c = l & 31;
            int m = bm + r, kg = k0 + c;
            int t = m & (Tt - 1);
            float hs = keyval[m*H + kg];
            float hp = (t > 0) ? keyval[(m-1)*H + kg] : 0.f;
            As[r][c] = fmaf(hp - hs, __ldg(&xm[kg]), hs);
            Ws[r][c] = W[(bn + r)*H + kg];
        }
        __syncthreads();
        #pragma unroll
        for (int kk = 0; kk < 32; kk++) {
            float a_[4], w_[4];
            #pragma unroll
            for (int i = 0; i < 4; i++) { a_[i] = As[ty + 16*i][kk]; w_[i] = Ws[tx + 16*i][kk]; }
            #pragma unroll
            for (int i = 0; i < 4; i++)
                #pragma unroll
                for (int jj = 0; jj < 4; jj++) acc[i][jj] = fmaf(a_[i], w_[jj], acc[i][jj]);
        }
        __syncthreads();
    }
    #pragma unroll
    for (int i = 0; i < 4; i++)
        #pragma unroll
        for (int jj = 0; jj < 4; jj++)
            C[(bm + ty + 16*i)*H + (bn + tx + 16*jj)] = acc[i][jj];
}

// ---------------- k3: per-(eb, pair) scan-input precompute (kk-normalize inline) ----------------
__global__ void k_pair(const float* __restrict__ v_first, const float* __restrict__ w2,
                       const float* __restrict__ w0, const float* __restrict__ a0,
                       const float* __restrict__ k_a, const float* __restrict__ k_k) {
    int p = blockIdx.x, eb = blockIdx.y;
    int b = eb >> 3;
    int t1 = 2*p + 1, t0 = 2*p;
    int bt1 = b*Tt + t1, bt0 = b*Tt + t0;
    int j = threadIdx.x;
    int w = j >> 5, ln = j & 31;
    __shared__ float th[2][32];
    __shared__ float wsq[2][8];
    __shared__ float sq[2][8];
    float kkj = k_k[j];
    float kkv1 = g_K[bt1*H + j] * kkj;
    float kkv0 = g_K[bt0*H + j] * kkj;
    float n1p = wsum(kkv1 * kkv1);
    float n0p = wsum(kkv0 * kkv0);
    if (ln == 0) { wsq[0][w] = n1p; wsq[1][w] = n0p; }
    if (j < 64) {
        int m = j >> 5, d = j & 31;
        int btx = m ? bt0 : bt1;
        th[m][d] = tanhf(g_Hw1[btx*32 + d] + g_qw1[eb*32 + d]);
    }
    __syncthreads();
    int head = j >> 6;
    float nrm1 = sqrtf(wsq[0][2*head] + wsq[0][2*head + 1]);
    float nrm0 = sqrtf(wsq[1][2*head] + wsq[1][2*head + 1]);
    float kk1 = kkv1 / fmaxf(nrm1, 1e-12f);
    float kk0 = kkv0 / fmaxf(nrm0, 1e-12f);
    float ac1 = 0.f, ac0 = 0.f;
    #pragma unroll
    for (int d = 0; d < 32; d++) {
        float wd = w2[d*H + j];
        ac1 = fmaf(th[0][d], wd, ac1);
        ac0 = fmaf(th[1][d], wd, ac0);
    }
    float w0j = w0[j], a0j = a0[j], kaj = k_a[j], qAj = g_qA[eb*H + j];
    float ew1 = __expf(NEGc * sigmoidf_(w0j + ac1));
    float ew0 = __expf(NEGc * sigmoidf_(w0j + ac0));
    float a41 = sigmoidf_(a0j + g_hA[bt1*H + j] + qAj);
    float a40 = sigmoidf_(a0j + g_hA[bt0*H + j] + qAj);
    float kf1 = g_K[bt1*H + j] * fmaf(a41 - 1.f, kaj, 1.f);
    float kf0 = g_K[bt0*H + j] * fmaf(a40 - 1.f, kaj, 1.f);
    float bv1 = kk1 * a41;
    float bv0 = kk0 * a40;
    float vb1 = g_Vb[bt1*H + j], sv1 = g_sigv[bt1*H + j];
    float vb0 = g_Vb[bt0*H + j], sv0 = g_sigv[bt0*H + j];
    float vv1 = fmaf(v_first[((size_t)eb*Tt + t1)*H + j] - vb1, sv1, vb1);
    float vv0 = fmaf(v_first[((size_t)eb*Tt + t0)*H + j] - vb0, sv0, vb0);
    size_t idx = ((size_t)eb*NP + p)*H + j;
    g_Pa[idx]  = make_float4(kf1, bv1, ew1*kf0, ew1*bv0);
    g_Pb[idx]  = make_float4(ew1*ew0, kk1*ew0, kk0, vv1);
    g_Pv0[idx] = vv0;
    float q1p = wsum(kk1 * kf0);
    float q2p = wsum(kk1 * bv0);
    if (ln == 0) { sq[0][w] = q1p; sq[1][w] = q2p; }
    __syncthreads();
    if (j < 4) {
        float q1 = sq[0][2*j] + sq[0][2*j + 1];
        float q2 = sq[1][2*j] + sq[1][2*j + 1];
        g_q[(eb*NP + p)*4 + j] = make_float2(q1, q2);
    }
}

// ---------------- k4: backward scan, 1 warp per (eb, head), 8-deep prefetch ring ----------------
#define PF 8
__global__ void __launch_bounds__(32) k_scan(const float* __restrict__ r_k,
                       const float* __restrict__ gn_w, const float* __restrict__ gn_b) {
    int wb = blockIdx.x;
    int eb = wb >> 2, h = wb & 3;
    int ln = threadIdx.x;
    int i0 = h*HD + ln, i1 = i0 + 32;
    float u0 = g_rlast[eb*H + i0], u1 = g_rlast[eb*H + i1];
    float o0 = 0.f, o1 = 0.f;
    const float4* __restrict__ Pa  = g_Pa  + (size_t)eb*NP*H;
    const float4* __restrict__ Pb  = g_Pb  + (size_t)eb*NP*H;
    const float*  __restrict__ Pv0 = g_Pv0 + (size_t)eb*NP*H;
    const float2* __restrict__ Qs  = g_q   + eb*NP*4;

    float4 A0[PF], A1[PF], B0[PF], B1[PF];
    float  V0[PF], V1[PF];
    float2 Qr[PF];
    #pragma unroll
    for (int s = 0; s < PF; s++) {
        int p = NP - 1 - s;
        size_t base = (size_t)p*H;
        A0[s] = Pa[base + i0]; A1[s] = Pa[base + i1];
        B0[s] = Pb[base + i0]; B1[s] = Pb[base + i1];
        V0[s] = Pv0[base + i0]; V1[s] = Pv0[base + i1];
        Qr[s] = Qs[p*4 + h];
    }
    #pragma unroll 1
    for (int p0 = NP - 1; p0 >= PF - 1; p0 -= PF) {
        #pragma unroll
        for (int s = 0; s < PF; s++) {
            int p = p0 - s;
            float4 cA0 = A0[s], cA1 = A1[s], cB0 = B0[s], cB1 = B1[s];
            float cV0 = V0[s], cV1 = V1[s];
            float2 cQ = Qr[s];
            // register-ring refill for p-PF
            int pn = p - PF;
            if (pn >= 0) {
                size_t nb = (size_t)pn*H;
                A0[s] = Pa[nb + i0]; A1[s] = Pa[nb + i1];
                B0[s] = Pb[nb + i0]; B1[s] = Pb[nb + i1];
                V0[s] = Pv0[nb + i0]; V1[s] = Pv0[nb + i1];
                Qr[s] = Qs[pn*4 + h];
            }
            // four independent reductions, interleaved butterflies
            float r1 = fmaf(u0, cA0.x, u1*cA1.x);   // c1 = u·kf1
            float r2 = fmaf(u0, cA0.y, u1*cA1.y);   // s1 = u·bv1
            float r3 = fmaf(u0, cA0.z, u1*cA1.z);   // m1 = u·(ew1∘kf0)
            float r4 = fmaf(u0, cA0.w, u1*cA1.w);   // m2 = u·(ew1∘bv0)
            #pragma unroll
            for (int off = 16; off; off >>= 1) {
                r1 += __shfl_xor_sync(0xffffffffu, r1, off);
                r2 += __shfl_xor_sync(0xffffffffu, r2, off);
                r3 += __shfl_xor_sync(0xffffffffu, r3, off);
                r4 += __shfl_xor_sync(0xffffffffu, r4, off);
            }
            float c0 = fmaf(-r2, cQ.x, r3);
            float s0 = fmaf(-r2, cQ.y, r4);
            o0 = fmaf(r1, cB0.w, fmaf(c0, cV0, o0));
            o1 = fmaf(r1, cB1.w, fmaf(c0, cV1, o1));
            u0 = fmaf(u0, cB0.x, -fmaf(r2, cB0.y, s0*cB0.z));
            u1 = fmaf(u1, cB1.x, -fmaf(r2, cB1.y, s0*cB1.z));
        }
    }
    // groupnorm over the head's 64 values
    float ms = wsum(o0 + o1);
    float sqs = wsum(fmaf(o0, o0, o1*o1));
    float mean = ms * (1.f/64.f);
    float var  = sqs * (1.f/64.f) - mean*mean;
    float inv  = rsqrtf(var + EPSc);
    float on0 = fmaf((o0 - mean)*inv, gn_w[i0], gn_b[i0]);
    float on1 = fmaf((o1 - mean)*inv, gn_w[i1], gn_b[i1]);
    // residual at t = T-1 (pair NP-1: kf1 = Pa.x, vv1 = Pb.w)
    size_t lb = (size_t)(NP-1)*H;
    float4 La0 = Pa[lb + i0], La1 = Pa[lb + i1];
    float4 Lb0 = Pb[lb + i0], Lb1 = Pb[lb + i1];
    float r0 = g_rlast[eb*H + i0], r1l = g_rlast[eb*H + i1];
    float rr = wsum(r0*La0.x*r_k[i0] + r1l*La1.x*r_k[i1]);
    on0 = fmaf(rr, Lb0.w, on0);
    on1 = fmaf(rr, Lb1.w, on1);
    g_o[eb*H + i0] = on0 * g_glast[eb*H + i0];
    g_o[eb*H + i1] = on1 * g_glast[eb*H + i1];
}

// ---------------- k5: out = g_o @ Wo^T (per-thread row dot) ----------------
__global__ void k_out(const float* __restrict__ Wo, float* __restrict__ out) {
    int eb = blockIdx.x; int j = threadIdx.x;
    __shared__ float os[H];
    os[j] = g_o[eb*H + j];
    __syncthreads();
    float acc = 0.f;
    const float4* __restrict__ Wrow = (const float4*)(Wo + j*H);
    #pragma unroll 16
    for (int k4 = 0; k4 < 64; k4++) {
        float4 wv = Wrow[k4];
        acc += os[4*k4]*wv.x + os[4*k4+1]*wv.y + os[4*k4+2]*wv.z + os[4*k4+3]*wv.w;
    }
    out[eb*H + j] = acc;
}

// ---------------- launch ----------------
extern "C" void kernel_launch(void* const* d_in, const int* in_sizes, int n_in,
                              void* d_out, int out_size) {
    const float* query   = (const float*)d_in[0];
    const float* keyval  = (const float*)d_in[1];
    const float* v_first = (const float*)d_in[2];
    const float* x_r = (const float*)d_in[3];
    const float* x_w = (const float*)d_in[4];
    const float* x_k = (const float*)d_in[5];
    const float* x_v = (const float*)d_in[6];
    const float* x_a = (const float*)d_in[7];
    const float* x_g = (const float*)d_in[8];
    const float* w0  = (const float*)d_in[9];
    const float* w1  = (const float*)d_in[10];
    const float* w2  = (const float*)d_in[11];
    const float* a0  = (const float*)d_in[12];
    const float* a1  = (const float*)d_in[13];
    const float* a2  = (const float*)d_in[14];
    const float* v0  = (const float*)d_in[15];
    const float* v1  = (const float*)d_in[16];
    const float* v2  = (const float*)d_in[17];
    const float* g1  = (const float*)d_in[18];
    const float* g2  = (const float*)d_in[19];
    const float* k_k = (const float*)d_in[20];
    const float* k_a = (const float*)d_in[21];
    const float* r_k = (const float*)d_in[22];
    const float* Wr  = (const float*)d_in[23];
    const float* Wk  = (const float*)d_in[24];
    const float* Wv  = (const float*)d_in[25];
    const float* Wo  = (const float*)d_in[26];
    const float* gn_w = (const float*)d_in[27];
    const float* gn_b = (const float*)d_in[28];
    float* out = (float*)d_out;

    k_btq<<<BT + EB, H>>>(keyval, query, x_v, x_w, x_a, x_r, x_g,
                          w1, v1, a1, v2, a2, v0, g1, g2, Wr);
    k_gemm_kv<<<dim3(BT/64, H/64, 2), 256>>>(keyval, x_k, x_v, Wk, Wv);
    k_pair<<<dim3(NP, EB), H>>>(v_first, w2, w0, a0, k_a, k_k);
    k_scan<<<EB*4, 32>>>(r_k, gn_w, gn_b);
    k_out<<<EB, H>>>(Wo, out);
    (void)in_sizes; (void)n_in; (void)out_size;
}

// round 9
// speedup vs baseline: 1.2720x; 1.0705x over previous
#include <cuda_runtime.h>
#include <math.h>

#define H   256
#define HD  64
#define NH  4
#define Bb  2
#define Qq  8
#define Tt  512
#define L   16           // chunk length (timesteps)
#define NC  32           // Tt / L
#define EB  16
#define BT  1024
#define NEGc (-0.6065306597126334f)
#define EPSc 0.00064f

// ---------------- scratch (device globals; no allocations) ----------------
__device__ float g_K  [BT*H];
__device__ float g_Vb [BT*H];
__device__ float g_sigv[BT*H];
__device__ float g_hA [BT*H];
__device__ float g_Hw1[BT*32];
__device__ float g_qw1[EB*32];
__device__ float g_qA [EB*H];
__device__ float g_rlast[EB*H];
__device__ float g_glast[EB*H];
__device__ float g_o  [EB*H];
// chunked scan inputs
__device__ float g_W [(size_t)EB*NC*L*H];   // Ŵ_i = P_i ∘ kf
__device__ float g_Bv[(size_t)EB*NC*L*H];   // B̂_i = P_i ∘ bv
__device__ float g_Nt[(size_t)EB*NC*L*H];   // ñ_m = kk / P_{m+1}
__device__ float g_Vv[(size_t)EB*NC*L*H];   // vv
__device__ float g_Ep[(size_t)EB*NC*H];     // Ê = P_L
__device__ float g_QK[(size_t)EB*NC*NH*L*L];
__device__ float g_QB[(size_t)EB*NC*NH*L*L];

__device__ __forceinline__ float sigmoidf_(float x) { return 1.f / (1.f + __expf(-x)); }

__device__ __forceinline__ float wsum(float v) {
    #pragma unroll
    for (int o = 16; o; o >>= 1) v += __shfl_xor_sync(0xffffffffu, v, o);
    return v;
}

// ---------------- k1: merged per-bt and per-eb small chains (unchanged from R8) ----------------
__global__ void k_btq(const float* __restrict__ keyval, const float* __restrict__ query,
                      const float* __restrict__ x_v, const float* __restrict__ x_w,
                      const float* __restrict__ x_a, const float* __restrict__ x_r,
                      const float* __restrict__ x_g,
                      const float* __restrict__ w1, const float* __restrict__ v1,
                      const float* __restrict__ a1, const float* __restrict__ v2,
                      const float* __restrict__ a2, const float* __restrict__ v0,
                      const float* __restrict__ g1, const float* __restrict__ g2,
                      const float* __restrict__ Wr) {
    int blk = blockIdx.x;
    int j = threadIdx.x;
    int w = j >> 5, ln = j & 31;
    __shared__ float s0[H], s1[H], s2[H], s3[H];
    __shared__ float red[4][8][32];
    __shared__ float mid[4][32];
    if (blk < BT) {
        int bt = blk, t = bt & (Tt - 1);
        float hs = keyval[bt*H + j];
        float hp = (t > 0) ? keyval[(bt-1)*H + j] : 0.f;
        s0[j] = fmaf(hp - hs, x_v[j], hs);   // xv
        s1[j] = hs * (1.f - x_w[j]);         // xwh
        s2[j] = hs * (1.f - x_a[j]);         // xah
        __syncthreads();
        int kbase = w * 32;
        float pw = 0.f, pv = 0.f, pa = 0.f;
        #pragma unroll
        for (int kk = 0; kk < 32; kk++) {
            int k = kbase + kk;
            pw = fmaf(s1[k], w1[k*32 + ln], pw);
            pv = fmaf(s0[k], v1[k*32 + ln], pv);
            pa = fmaf(s2[k], a1[k*32 + ln], pa);
        }
        red[0][w][ln] = pw; red[1][w][ln] = pv; red[2][w][ln] = pa;
        __syncthreads();
        if (j < 96) {
            int m = j >> 5, d = j & 31;
            float s = 0.f;
            #pragma unroll
            for (int ww = 0; ww < 8; ww++) s += red[m][ww][d];
            mid[m][d] = s;
            if (m == 0) g_Hw1[bt*32 + d] = s;
        }
        __syncthreads();
        float av = 0.f, aa = 0.f;
        #pragma unroll
        for (int d = 0; d < 32; d++) {
            av = fmaf(mid[1][d], v2[d*H + j], av);
            aa = fmaf(mid[2][d], a2[d*H + j], aa);
        }
        g_sigv[bt*H + j] = sigmoidf_(av + v0[j]);
        g_hA[bt*H + j]   = aa;
    } else {
        int eb = blk - BT; int b = eb >> 3;
        float qv  = query[eb*H + j];
        float hsL = keyval[(b*Tt + Tt - 1)*H + j];
        s0[j] = fmaf(qv - hsL, x_r[j], hsL);  // xr
        s1[j] = fmaf(qv - hsL, x_g[j], hsL);  // xg
        s2[j] = qv * x_w[j];                  // xw (query part)
        s3[j] = qv * x_a[j];                  // xa (query part)
        __syncthreads();
        int kbase = w * 32;
        float pw = 0.f, pa = 0.f, pg0 = 0.f, pg1 = 0.f;
        #pragma unroll
        for (int kk = 0; kk < 32; kk++) {
            int k = kbase + kk;
            pw  = fmaf(s2[k], w1[k*32 + ln], pw);
            pa  = fmaf(s3[k], a1[k*32 + ln], pa);
            pg0 = fmaf(s1[k], g1[k*64 + ln], pg0);
            pg1 = fmaf(s1[k], g1[k*64 + 32 + ln], pg1);
        }
        red[0][w][ln] = pw; red[1][w][ln] = pa; red[2][w][ln] = pg0; red[3][w][ln] = pg1;
        __syncthreads();
        if (j < 128) {
            int m = j >> 5, d = j & 31;
            float s = 0.f;
            #pragma unroll
            for (int ww = 0; ww < 8; ww++) s += red[m][ww][d];
            if      (m == 0) g_qw1[eb*32 + d] = s;
            else if (m == 1) mid[1][d] = s;               // ta
            else if (m == 2) mid[2][d] = sigmoidf_(s);    // tg[0:32]
            else             mid[3][d] = sigmoidf_(s);    // tg[32:64]
        }
        __syncthreads();
        float aa = 0.f, gg = 0.f;
        #pragma unroll
        for (int d = 0; d < 32; d++) {
            aa = fmaf(mid[1][d], a2[d*H + j], aa);
            gg = fmaf(mid[2][d], g2[d*H + j], gg);
        }
        #pragma unroll
        for (int d = 0; d < 32; d++) gg = fmaf(mid[3][d], g2[(32 + d)*H + j], gg);
        g_qA[eb*H + j]    = aa;
        g_glast[eb*H + j] = gg;
        float acc = 0.f;
        const float4* __restrict__ Wrow = (const float4*)(Wr + j*H);
        #pragma unroll 16
        for (int k4 = 0; k4 < 64; k4++) {
            float4 wv = Wrow[k4];
            acc += s0[4*k4]*wv.x + s0[4*k4+1]*wv.y + s0[4*k4+2]*wv.z + s0[4*k4+3]*wv.w;
        }
        g_rlast[eb*H + j] = acc;
    }
}

// ---------------- k2: K = Xk@Wk^T, Vb = Xv@Wv^T (unchanged from R8) ----------------
__global__ void k_gemm_kv(const float* __restrict__ keyval,
                          const float* __restrict__ x_k, const float* __restrict__ x_v,
                          const float* __restrict__ Wk, const float* __restrict__ Wv) {
    const int z = blockIdx.z;
    const float* __restrict__ xm = z ? x_v : x_k;
    const float* __restrict__ W  = z ? Wv  : Wk;
    float* __restrict__ C = z ? g_Vb : g_K;
    __shared__ float As[64][33];
    __shared__ float Ws[64][33];
    int tid = threadIdx.x;
    int tx = tid & 15, ty = tid >> 4;
    int bm = blockIdx.x * 64, bn = blockIdx.y * 64;
    float acc[4][4] = {};
    #pragma unroll 1
    for (int k0 = 0; k0 < H; k0 += 32) {
        #pragma unroll
        for (int l = tid; l < 64*32; l += 256) {
            int r = l >> 5, c = l & 31;
            int m = bm + r, kg = k0 + c;
            int t = m & (Tt - 1);
            float hs = keyval[m*H + kg];
            float hp = (t > 0) ? keyval[(m-1)*H + kg] : 0.f;
            As[r][c] = fmaf(hp - hs, __ldg(&xm[kg]), hs);
            Ws[r][c] = W[(bn + r)*H + kg];
        }
        __syncthreads();
        #pragma unroll
        for (int kk = 0; kk < 32; kk++) {
            float a_[4], w_[4];
            #pragma unroll
            for (int i = 0; i < 4; i++) { a_[i] = As[ty + 16*i][kk]; w_[i] = Ws[tx + 16*i][kk]; }
            #pragma unroll
            for (int i = 0; i < 4; i++)
                #pragma unroll
                for (int jj = 0; jj < 4; jj++) acc[i][jj] = fmaf(a_[i], w_[jj], acc[i][jj]);
        }
        __syncthreads();
    }
    #pragma unroll
    for (int i = 0; i < 4; i++)
        #pragma unroll
        for (int jj = 0; jj < 4; jj++)
            C[(bm + ty + 16*i)*H + (bn + tx + 16*jj)] = acc[i][jj];
}

// ---------------- k3: per-(eb, chunk) precompute of chunked-scan inputs ----------------
// chunk p covers t in [pL, pL+L); backward index i: t(i) = pL + (L-1) - i.
__global__ void k_chunk(const float* __restrict__ v_first, const float* __restrict__ w2,
                        const float* __restrict__ w0, const float* __restrict__ a0,
                        const float* __restrict__ k_a, const float* __restrict__ k_k) {
    int p = blockIdx.x, eb = blockIdx.y;
    int b = eb >> 3;
    int j = threadIdx.x;             // 256
    int w = j >> 5, ln = j & 31;
    __shared__ float th[L][32];
    __shared__ float sN[L][H+1];
    __shared__ float sW[L][H+1];
    __shared__ float nb[8];
    // load + tanh the w-path mids for all L timesteps
    for (int idx = j; idx < L*32; idx += 256) {
        int i = idx >> 5, d = idx & 31;
        int t = p*L + (L-1) - i;
        th[i][d] = tanhf(g_Hw1[(b*Tt + t)*32 + d] + g_qw1[eb*32 + d]);
    }
    __syncthreads();
    float w0j = w0[j], a0j = a0[j], kaj = k_a[j], kkj = k_k[j], qAj = g_qA[eb*H + j];
    float w2c[32];
    #pragma unroll
    for (int d = 0; d < 32; d++) w2c[d] = w2[d*H + j];
    float P = 1.f;
    #pragma unroll 1
    for (int i = 0; i < L; i++) {
        int t = p*L + (L-1) - i;
        int bt = b*Tt + t;
        float ac = 0.f;
        #pragma unroll
        for (int d = 0; d < 32; d++) ac = fmaf(th[i][d], w2c[d], ac);
        float ew = __expf(NEGc * sigmoidf_(w0j + ac));
        float Kv = g_K[bt*H + j];
        float kkv = Kv * kkj;
        float sqp = wsum(kkv * kkv);
        if (ln == 0) nb[w] = sqp;
        __syncthreads();
        int head = j >> 6;
        float nrm = sqrtf(nb[2*head] + nb[2*head + 1]);
        float kk = kkv / fmaxf(nrm, 1e-12f);
        __syncthreads();      // guard nb before next iteration's write
        float a4 = sigmoidf_(a0j + g_hA[bt*H + j] + qAj);
        float kf = Kv * fmaf(a4 - 1.f, kaj, 1.f);
        float bvv = kk * a4;
        float vb = g_Vb[bt*H + j], sv = g_sigv[bt*H + j];
        float vv = fmaf(v_first[((size_t)eb*Tt + t)*H + j] - vb, sv, vb);
        float Wi = P * kf;
        float Bi = P * bvv;
        float Ni = kk / (P * ew);      // P_{i+1} = P * ew
        sN[i][j] = Ni; sW[i][j] = Wi;
        size_t o = (((size_t)eb*NC + p)*L + i)*H + j;
        g_W[o] = Wi; g_Bv[o] = Bi; g_Nt[o] = Ni; g_Vv[o] = vv;
        P *= ew;
    }
    g_Ep[((size_t)eb*NC + p)*H + j] = P;
    __syncthreads();
    // QK[m][i] = ñ_m · Ŵ_i (per head, m < i)
    size_t qbase = (((size_t)eb*NC + p)*NH) * (L*L);
    for (int idx = j; idx < NH*120; idx += 256) {
        int hh = idx / 120;
        int r = idx % 120;
        int i = (int)((1.0f + sqrtf(1.0f + 8.0f*(float)r)) * 0.5f);
        int tri = (i*(i-1)) >> 1;
        if (r < tri) { i--; tri = (i*(i-1)) >> 1; }
        else if (r >= tri + i) { i++; tri = (i*(i-1)) >> 1; }
        int m = r - tri;
        int base = hh * 64;
        float acc = 0.f;
        #pragma unroll
        for (int d = 0; d < 64; d++) acc = fmaf(sN[m][base+d], sW[i][base+d], acc);
        g_QK[qbase + (size_t)hh*(L*L) + m*L + i] = acc;
    }
    __syncthreads();
    // reload B̂ into sW (L2-hot), then QB
    for (int idx = j; idx < L*H; idx += 256) {
        int i = idx >> 8, d = idx & 255;
        sW[i][d] = g_Bv[(((size_t)eb*NC + p)*L + i)*H + d];
    }
    __syncthreads();
    for (int idx = j; idx < NH*120; idx += 256) {
        int hh = idx / 120;
        int r = idx % 120;
        int i = (int)((1.0f + sqrtf(1.0f + 8.0f*(float)r)) * 0.5f);
        int tri = (i*(i-1)) >> 1;
        if (r < tri) { i--; tri = (i*(i-1)) >> 1; }
        else if (r >= tri + i) { i++; tri = (i*(i-1)) >> 1; }
        int m = r - tri;
        int base = hh * 64;
        float acc = 0.f;
        #pragma unroll
        for (int d = 0; d < 64; d++) acc = fmaf(sN[m][base+d], sW[i][base+d], acc);
        g_QB[qbase + (size_t)hh*(L*L) + m*L + i] = acc;
    }
}

// ---------------- k4: chunked backward scan, 256 threads per (eb, head) ----------------
__global__ void __launch_bounds__(256) k_scan(const float* __restrict__ r_k,
                        const float* __restrict__ gn_w, const float* __restrict__ gn_b) {
    int blk = blockIdx.x;
    int eb = blk >> 2, h = blk & 3;
    int tid = threadIdx.x;
    int jb = h * 64;
    __shared__ float su[64], so[64];
    __shared__ float rs[L], es[L], cs[L], ss[L];
    __shared__ float pu[4][64], po[4][64];
    __shared__ float r1s[64], r2s[64], r3s[64];
    __shared__ float fin[3];
    if (tid < 64) { su[tid] = g_rlast[eb*H + jb + tid]; so[tid] = 0.f; }
    __syncthreads();
    int i16 = tid >> 4;   // reduction-vector index 0..15
    int jg  = tid & 15;   // dim group (4 dims each)
    int q   = tid >> 6;   // m-quarter for phase3
    int jj  = tid & 63;   // dim for phase3
    // prefetch phase-1 vectors for chunk NC-1
    float4 wv, bvv;
    {
        size_t cb0 = ((size_t)eb*NC + (NC-1))*L*H + jb;
        wv  = *((const float4*)(g_W  + cb0 + (size_t)i16*H) + jg);
        bvv = *((const float4*)(g_Bv + cb0 + (size_t)i16*H) + jg);
    }
    #pragma unroll 1
    for (int p = NC - 1; p >= 0; --p) {
        size_t cb = ((size_t)eb*NC + p)*L*H + jb;
        // early loads used later this iteration
        float vN[4], vV[4];
        #pragma unroll
        for (int mm = 0; mm < 4; mm++) {
            size_t off = cb + (size_t)(q*4 + mm)*H + jj;
            vN[mm] = g_Nt[off];
            vV[mm] = g_Vv[off];
        }
        float Ereg = 0.f;
        if (tid < 64) Ereg = g_Ep[((size_t)eb*NC + p)*H + jb + tid];
        float qkcol[L], qbcol[L];
        if (tid < 16) {
            size_t qb = (((size_t)eb*NC + p)*NH + h)*(L*L);
            #pragma unroll
            for (int m = 0; m < L; m++) {
                qkcol[m] = g_QK[qb + m*L + tid];
                qbcol[m] = g_QB[qb + m*L + tid];
            }
        }
        // phase 1: raw dots r_i = u·Ŵ_i, e_i = u·B̂_i
        float u0 = su[jg*4], u1 = su[jg*4+1], u2 = su[jg*4+2], u3 = su[jg*4+3];
        float pr = u0*wv.x + u1*wv.y + u2*wv.z + u3*wv.w;
        float pe = u0*bvv.x + u1*bvv.y + u2*bvv.z + u3*bvv.w;
        // prefetch next chunk's phase-1 vectors (independent of solve)
        if (p > 0) {
            size_t cbn = ((size_t)eb*NC + (p-1))*L*H + jb;
            wv  = *((const float4*)(g_W  + cbn + (size_t)i16*H) + jg);
            bvv = *((const float4*)(g_Bv + cbn + (size_t)i16*H) + jg);
        }
        #pragma unroll
        for (int off = 8; off; off >>= 1) {
            pr += __shfl_xor_sync(0xffffffffu, pr, off);
            pe += __shfl_xor_sync(0xffffffffu, pe, off);
        }
        if (jg == 0) { rs[i16] = pr; es[i16] = pe; }
        __syncthreads();
        // phase 2: triangular solve (lanes 0..15 of warp 0)
        if (tid < 16) {
            float c = rs[tid], s = es[tid];
            #pragma unroll
            for (int m = 0; m < L-1; m++) {
                float sm = __shfl_sync(0x0000ffffu, s, m, 16);
                if (tid > m) {
                    c = fmaf(-sm, qkcol[m], c);
                    s = fmaf(-sm, qbcol[m], s);
                }
            }
            cs[tid] = c; ss[tid] = s;
        }
        __syncthreads();
        // phase 3: partial o/u updates
        float accO = 0.f, accU = 0.f;
        #pragma unroll
        for (int mm = 0; mm < 4; mm++) {
            int m = q*4 + mm;
            accO = fmaf(cs[m], vV[mm], accO);
            accU = fmaf(ss[m], vN[mm], accU);
        }
        po[q][jj] = accO; pu[q][jj] = accU;
        __syncthreads();
        if (tid < 64) {
            so[tid] += po[0][tid] + po[1][tid] + po[2][tid] + po[3][tid];
            su[tid] = Ereg * (su[tid] - (pu[0][tid] + pu[1][tid] + pu[2][tid] + pu[3][tid]));
        }
        __syncthreads();
    }
    // epilogue: groupnorm + residual + gate
    if (tid < 64) {
        float o = so[tid];
        r1s[tid] = o;
        r2s[tid] = o*o;
        size_t lw = (((size_t)eb*NC + (NC-1))*L + 0)*H + jb + tid;  // kf at t=T-1
        r3s[tid] = g_rlast[eb*H + jb + tid] * g_W[lw] * r_k[jb + tid];
    }
    __syncthreads();
    if (tid < 32) {
        r1s[tid] += r1s[tid + 32];
        r2s[tid] += r2s[tid + 32];
        r3s[tid] += r3s[tid + 32];
        float a = wsum(r1s[tid]);
        float b2 = wsum(r2s[tid]);
        float c = wsum(r3s[tid]);
        if (tid == 0) { fin[0] = a; fin[1] = b2; fin[2] = c; }
    }
    __syncthreads();
    if (tid < 64) {
        float mean = fin[0] * (1.f/64.f);
        float var  = fin[1] * (1.f/64.f) - mean*mean;
        float inv  = rsqrtf(var + EPSc);
        float on = fmaf((so[tid] - mean)*inv, gn_w[jb + tid], gn_b[jb + tid]);
        size_t lv = (((size_t)eb*NC + (NC-1))*L + 0)*H + jb + tid;  // vv at t=T-1
        on = fmaf(fin[2], g_Vv[lv], on);
        g_o[eb*H + jb + tid] = on * g_glast[eb*H + jb + tid];
    }
}

// ---------------- k5: out = g_o @ Wo^T (per-thread row dot) ----------------
__global__ void k_out(const float* __restrict__ Wo, float* __restrict__ out) {
    int eb = blockIdx.x; int j = threadIdx.x;
    __shared__ float os[H];
    os[j] = g_o[eb*H + j];
    __syncthreads();
    float acc = 0.f;
    const float4* __restrict__ Wrow = (const float4*)(Wo + j*H);
    #pragma unroll 16
    for (int k4 = 0; k4 < 64; k4++) {
        float4 wv = Wrow[k4];
        acc += os[4*k4]*wv.x + os[4*k4+1]*wv.y + os[4*k4+2]*wv.z + os[4*k4+3]*wv.w;
    }
    out[eb*H + j] = acc;
}

// ---------------- launch ----------------
extern "C" void kernel_launch(void* const* d_in, const int* in_sizes, int n_in,
                              void* d_out, int out_size) {
    const float* query   = (const float*)d_in[0];
    const float* keyval  = (const float*)d_in[1];
    const float* v_first = (const float*)d_in[2];
    const float* x_r = (const float*)d_in[3];
    const float* x_w = (const float*)d_in[4];
    const float* x_k = (const float*)d_in[5];
    const float* x_v = (const float*)d_in[6];
    const float* x_a = (const float*)d_in[7];
    const float* x_g = (const float*)d_in[8];
    const float* w0  = (const float*)d_in[9];
    const float* w1  = (const float*)d_in[10];
    const float* w2  = (const float*)d_in[11];
    const float* a0  = (const float*)d_in[12];
    const float* a1  = (const float*)d_in[13];
    const float* a2  = (const float*)d_in[14];
    const float* v0  = (const float*)d_in[15];
    const float* v1  = (const float*)d_in[16];
    const float* v2  = (const float*)d_in[17];
    const float* g1  = (const float*)d_in[18];
    const float* g2  = (const float*)d_in[19];
    const float* k_k = (const float*)d_in[20];
    const float* k_a = (const float*)d_in[21];
    const float* r_k = (const float*)d_in[22];
    const float* Wr  = (const float*)d_in[23];
    const float* Wk  = (const float*)d_in[24];
    const float* Wv  = (const float*)d_in[25];
    const float* Wo  = (const float*)d_in[26];
    const float* gn_w = (const float*)d_in[27];
    const float* gn_b = (const float*)d_in[28];
    float* out = (float*)d_out;

    k_btq<<<BT + EB, H>>>(keyval, query, x_v, x_w, x_a, x_r, x_g,
                          w1, v1, a1, v2, a2, v0, g1, g2, Wr);
    k_gemm_kv<<<dim3(BT/64, H/64, 2), 256>>>(keyval, x_k, x_v, Wk, Wv);
    k_chunk<<<dim3(NC, EB), 256>>>(v_first, w2, w0, a0, k_a, k_k);
    k_scan<<<EB*NH, 256>>>(r_k, gn_w, gn_b);
    k_out<<<EB, H>>>(Wo, out);
    (void)in_sizes; (void)n_in; (void)out_size;
}